// round 1
// baseline (speedup 1.0000x reference)
#include <cuda_runtime.h>
#include <math.h>

// Problem constants
#define N_TOTAL 8192
#define HALF_N  4096
#define D       128
#define D4      32          // D / 4 (float4 per row)

// Tiling
#define BM      128
#define BN      128
#define DPAD    132         // padded row stride in floats (16B-aligned, conflict-free)
#define THREADS 256
#define SMEM_BYTES (2 * BM * DPAD * 4)

__device__ float g_norm[N_TOTAL];
__device__ float g_rowsum[N_TOTAL];
__device__ float g_diag[HALF_N];

// ---------------------------------------------------------------------------
// Kernel 1: per-row squared norms, diag_ab sims, and rowsum zeroing.
// One warp per row; each lane holds one float4 of the row.
// ---------------------------------------------------------------------------
__global__ void prep_kernel(const float* __restrict__ X) {
    int warp = (blockIdx.x * blockDim.x + threadIdx.x) >> 5;
    int lane = threadIdx.x & 31;
    if (warp >= N_TOTAL) return;
    const float4* X4 = (const float4*)X;

    float4 v = X4[warp * D4 + lane];
    float s = v.x * v.x + v.y * v.y + v.z * v.z + v.w * v.w;
    #pragma unroll
    for (int off = 16; off; off >>= 1) s += __shfl_xor_sync(0xffffffffu, s, off);
    if (lane == 0) {
        g_norm[warp] = s;
        g_rowsum[warp] = 0.0f;
    }

    if (warp < HALF_N) {
        float4 w = X4[(warp + HALF_N) * D4 + lane];
        float dx = v.x - w.x, dy = v.y - w.y, dz = v.z - w.z, dw = v.w - w.w;
        float sq = dx * dx + dy * dy + dz * dz + dw * dw;
        #pragma unroll
        for (int off = 16; off; off >>= 1) sq += __shfl_xor_sync(0xffffffffu, sq, off);
        if (lane == 0) g_diag[warp] = 1.0f / (fmaxf(sq, 0.0f) + 1.0f);
    }
}

// ---------------------------------------------------------------------------
// Kernel 2: full-matrix Cauchy row sums.
// Grid (64, 2): blockIdx.x = 128-row tile, blockIdx.y = which half of columns.
// A tile (this block's 128 rows, K=128) resident in smem for the whole block;
// B tiles (128 cols x 128) streamed. 16x16 threads, 8x8 interleaved micro-tile.
// ---------------------------------------------------------------------------
__global__ void __launch_bounds__(THREADS, 1)
simsum_kernel(const float* __restrict__ X) {
    extern __shared__ float smem[];
    float* As = smem;               // [BM][DPAD]
    float* Bs = smem + BM * DPAD;   // [BN][DPAD]

    const int tid = threadIdx.x;
    const int tx = tid & 15;        // column group
    const int ty = tid >> 4;        // row group
    const int row0 = blockIdx.x * BM;
    const int jtile0 = blockIdx.y * 32;   // 32 column tiles per half

    const float4* X4 = (const float4*)X;

    // Load A tile (coalesced; conflict-free stores: fixed row, c4 = lane)
    #pragma unroll
    for (int it = 0; it < (BM * D4) / THREADS; ++it) {
        int idx = it * THREADS + tid;
        int r = idx >> 5, c4 = idx & 31;
        ((float4*)(As + r * DPAD))[c4] = X4[(row0 + r) * D4 + c4];
    }

    float nI[8];
    #pragma unroll
    for (int m = 0; m < 8; ++m) nI[m] = g_norm[row0 + ty + 16 * m];

    float rsum[8];
    #pragma unroll
    for (int m = 0; m < 8; ++m) rsum[m] = 0.0f;

    for (int jt = 0; jt < 32; ++jt) {
        int col0 = (jtile0 + jt) * BN;

        __syncthreads();   // previous tile's compute done before overwrite
        #pragma unroll
        for (int it = 0; it < (BN * D4) / THREADS; ++it) {
            int idx = it * THREADS + tid;
            int r = idx >> 5, c4 = idx & 31;
            ((float4*)(Bs + r * DPAD))[c4] = X4[(col0 + r) * D4 + c4];
        }
        __syncthreads();

        float acc[8][8];
        #pragma unroll
        for (int m = 0; m < 8; ++m)
            #pragma unroll
            for (int n = 0; n < 8; ++n) acc[m][n] = 0.0f;

        #pragma unroll 2
        for (int k4 = 0; k4 < D4; ++k4) {
            float4 a4[8], b4[8];
            #pragma unroll
            for (int m = 0; m < 8; ++m)
                a4[m] = ((const float4*)(As + (ty + 16 * m) * DPAD))[k4];
            #pragma unroll
            for (int n = 0; n < 8; ++n)
                b4[n] = ((const float4*)(Bs + (tx + 16 * n) * DPAD))[k4];
            #pragma unroll
            for (int m = 0; m < 8; ++m)
                #pragma unroll
                for (int n = 0; n < 8; ++n) {
                    acc[m][n] = fmaf(a4[m].x, b4[n].x, acc[m][n]);
                    acc[m][n] = fmaf(a4[m].y, b4[n].y, acc[m][n]);
                    acc[m][n] = fmaf(a4[m].z, b4[n].z, acc[m][n]);
                    acc[m][n] = fmaf(a4[m].w, b4[n].w, acc[m][n]);
                }
        }

        // Epilogue: sim = 1 / (nI + nJ - 2*dot + 1), accumulate row sums.
        float nJ[8];
        #pragma unroll
        for (int n = 0; n < 8; ++n) nJ[n] = __ldg(&g_norm[col0 + tx + 16 * n]);

        #pragma unroll
        for (int m = 0; m < 8; ++m) {
            float rs = 0.0f;
            #pragma unroll
            for (int n = 0; n < 8; ++n) {
                float sq = fmaf(-2.0f, acc[m][n], nI[m] + nJ[n]);
                sq = fmaxf(sq, 0.0f);
                rs += __fdividef(1.0f, sq + 1.0f);
            }
            rsum[m] += rs;
        }
    }

    #pragma unroll
    for (int m = 0; m < 8; ++m)
        atomicAdd(&g_rowsum[row0 + ty + 16 * m], rsum[m]);
}

// ---------------------------------------------------------------------------
// Kernel 3: final reductions -> scalar loss.
// loss = -(mean(log diag_ab) - 0.5*(mean(log(rowfull_b - 1)) + mean(log(rowfull_a - 1))))
// ---------------------------------------------------------------------------
__global__ void finalize_kernel(float* __restrict__ out) {
    __shared__ float sA[1024], s1[1024], s2[1024];
    int tid = threadIdx.x;
    float tA = 0.0f, t1 = 0.0f, t2 = 0.0f;
    for (int i = tid; i < HALF_N; i += 1024) {
        tA += logf(g_diag[i]);
        t2 += logf(g_rowsum[i] - 1.0f);            // logsumexp_2 (a rows)
        t1 += logf(g_rowsum[i + HALF_N] - 1.0f);   // logsumexp_1 (b rows)
    }
    sA[tid] = tA; s1[tid] = t1; s2[tid] = t2;
    __syncthreads();
    for (int s = 512; s; s >>= 1) {
        if (tid < s) {
            sA[tid] += sA[tid + s];
            s1[tid] += s1[tid + s];
            s2[tid] += s2[tid + s];
        }
        __syncthreads();
    }
    if (tid == 0) {
        float align = sA[0] * (1.0f / HALF_N);
        float lse1  = s1[0] * (1.0f / HALF_N);
        float lse2  = s2[0] * (1.0f / HALF_N);
        out[0] = -(align - 0.5f * (lse1 + lse2));
    }
}

// ---------------------------------------------------------------------------
extern "C" void kernel_launch(void* const* d_in, const int* in_sizes, int n_in,
                              void* d_out, int out_size) {
    const float* X = (const float*)d_in[0];
    float* out = (float*)d_out;

    cudaFuncSetAttribute(simsum_kernel,
                         cudaFuncAttributeMaxDynamicSharedMemorySize, SMEM_BYTES);

    prep_kernel<<<N_TOTAL / 8, 256>>>(X);           // 8 warps/block, 1 row/warp
    dim3 grid(N_TOTAL / BM, 2);
    simsum_kernel<<<grid, THREADS, SMEM_BYTES>>>(X);
    finalize_kernel<<<1, 1024>>>(out);
}

// round 3
// speedup vs baseline: 4.3562x; 4.3562x over previous
#include <cuda_runtime.h>
#include <cuda_bf16.h>
#include <math.h>
#include <stdint.h>

#define N_TOTAL 8192
#define HALF_N  4096
#define KD      256              // split K: [hi | lo] bf16
#define BM      128
#define BN      128
#define PITCHB  528              // padded row pitch in bytes (264 bf16)

#define SMEM_A   0
#define SMEM_B   (128 * PITCHB)
#define SMEM_NI  (256 * PITCHB)               // 128 floats
#define SMEM_NJ  (256 * PITCHB + 512)         // 128 floats
#define SMEM_TOTAL (256 * PITCHB + 1024)

__device__ __align__(16) __nv_bfloat16 g_Y[N_TOTAL * KD];   // 4 MB scratch
__device__ float g_norm[N_TOTAL];
__device__ float g_rowsum[N_TOTAL];
__device__ float g_diag[HALF_N];

// ---------------------------------------------------------------- helpers
__device__ __forceinline__ uint32_t smem_u32(const void* p) {
    uint32_t a;
    asm("{ .reg .u64 t; cvta.to.shared.u64 t, %1; cvt.u32.u64 %0, t; }"
        : "=r"(a) : "l"(p));
    return a;
}
__device__ __forceinline__ void cp_async16(uint32_t dst, const void* src) {
    asm volatile("cp.async.cg.shared.global [%0], [%1], 16;"
                 :: "r"(dst), "l"(src) : "memory");
}
__device__ __forceinline__ void cp_commit() {
    asm volatile("cp.async.commit_group;" ::: "memory");
}
template <int N>
__device__ __forceinline__ void cp_wait() {
    asm volatile("cp.async.wait_group %0;" :: "n"(N) : "memory");
}
__device__ __forceinline__ void mma_bf16(float* c, const uint32_t* a, const uint32_t* b) {
    asm volatile(
        "mma.sync.aligned.m16n8k16.row.col.f32.bf16.bf16.f32 "
        "{%0,%1,%2,%3}, {%4,%5,%6,%7}, {%8,%9}, {%0,%1,%2,%3};"
        : "+f"(c[0]), "+f"(c[1]), "+f"(c[2]), "+f"(c[3])
        : "r"(a[0]), "r"(a[1]), "r"(a[2]), "r"(a[3]), "r"(b[0]), "r"(b[1]));
}

// ---------------------------------------------------------------------------
// Kernel 1: norms (fp32), diag sims (fp32), rowsum zero, bf16 hi/lo split.
// One warp per row.
// ---------------------------------------------------------------------------
__global__ void prep_kernel(const float* __restrict__ X) {
    int warp = (blockIdx.x * blockDim.x + threadIdx.x) >> 5;
    int lane = threadIdx.x & 31;
    if (warp >= N_TOTAL) return;
    const float4* X4 = (const float4*)X;

    float4 v = X4[warp * 32 + lane];
    float s = v.x * v.x + v.y * v.y + v.z * v.z + v.w * v.w;
    #pragma unroll
    for (int off = 16; off; off >>= 1) s += __shfl_xor_sync(0xffffffffu, s, off);
    if (lane == 0) { g_norm[warp] = s; g_rowsum[warp] = 0.0f; }

    __nv_bfloat16 hx = __float2bfloat16(v.x), hy = __float2bfloat16(v.y);
    __nv_bfloat16 hz = __float2bfloat16(v.z), hw = __float2bfloat16(v.w);
    __nv_bfloat16 lx = __float2bfloat16(v.x - __bfloat162float(hx));
    __nv_bfloat16 ly = __float2bfloat16(v.y - __bfloat162float(hy));
    __nv_bfloat16 lz = __float2bfloat16(v.z - __bfloat162float(hz));
    __nv_bfloat16 lw = __float2bfloat16(v.w - __bfloat162float(hw));
    __nv_bfloat162* Yrow = (__nv_bfloat162*)(g_Y + (size_t)warp * KD);
    Yrow[lane * 2]          = __halves2bfloat162(hx, hy);
    Yrow[lane * 2 + 1]      = __halves2bfloat162(hz, hw);
    Yrow[64 + lane * 2]     = __halves2bfloat162(lx, ly);
    Yrow[64 + lane * 2 + 1] = __halves2bfloat162(lz, lw);

    if (warp < HALF_N) {
        float4 w = X4[(warp + HALF_N) * 32 + lane];
        float dx = v.x - w.x, dy = v.y - w.y, dz = v.z - w.z, dw = v.w - w.w;
        float sq = dx * dx + dy * dy + dz * dz + dw * dw;
        #pragma unroll
        for (int off = 16; off; off >>= 1) sq += __shfl_xor_sync(0xffffffffu, sq, off);
        if (lane == 0) g_diag[warp] = 1.0f / (fmaxf(sq, 0.0f) + 1.0f);
    }
}

// ---------------------------------------------------------------------------
// Kernel 2: upper-triangular 128x128 tiles via mma.sync bf16 (K=256).
// Off-diagonal tiles contribute row sums AND column sums (symmetry).
// 256 threads = 8 warps as 2(m) x 4(n); warp tile 64x32.
// ---------------------------------------------------------------------------
__global__ void __launch_bounds__(256, 1)
simsum_kernel() {
    const int bi = blockIdx.x, bj = blockIdx.y;
    if (bj < bi) return;
    const int row0 = bi * BM, col0 = bj * BN;

    extern __shared__ char smem[];
    const uint32_t sb = smem_u32(smem);
    float* nIs = (float*)(smem + SMEM_NI);
    float* nJs = (float*)(smem + SMEM_NJ);

    const int tid = threadIdx.x;
    const int wid = tid >> 5, lid = tid & 31;
    const int wm = wid >> 2, wn = wid & 3;     // warp grid 2x4
    const int g = lid >> 2, t = lid & 3;

    // norms into smem
    if (tid < 128) nIs[tid] = g_norm[row0 + tid];
    else           nJs[tid - 128] = g_norm[col0 + tid - 128];

    // Two-stage cp.async: stage h covers k-bytes [h*256, h*256+256) of all rows.
    #pragma unroll
    for (int h = 0; h < 2; ++h) {
        #pragma unroll
        for (int it = 0; it < 16; ++it) {
            int chunk = it * 256 + tid;       // 0..4095
            int r = chunk >> 4;               // 0..255 (0-127: A, 128-255: B)
            int c = chunk & 15;               // 16B chunk within 256B half-row
            int grow = (r < 128) ? (row0 + r) : (col0 + r - 128);
            const char* src = (const char*)g_Y + (size_t)grow * 512 + h * 256 + c * 16;
            cp_async16(sb + r * PITCHB + h * 256 + c * 16, src);
        }
        cp_commit();
    }

    float acc[4][4][4];
    #pragma unroll
    for (int mt = 0; mt < 4; ++mt)
        #pragma unroll
        for (int nt = 0; nt < 4; ++nt)
            #pragma unroll
            for (int e = 0; e < 4; ++e) acc[mt][nt][e] = 0.0f;

    const char* aptr = smem + SMEM_A + (wm * 64 + g) * PITCHB + t * 4;
    const char* bptr = smem + SMEM_B + (wn * 32 + g) * PITCHB + t * 4;

    #pragma unroll
    for (int h = 0; h < 2; ++h) {
        if (h == 0) cp_wait<1>(); else cp_wait<0>();
        __syncthreads();

        #pragma unroll
        for (int s = 0; s < 8; ++s) {
            const int kb = h * 256 + s * 32;
            uint32_t a[4][4], b[4][2];
            #pragma unroll
            for (int mt = 0; mt < 4; ++mt) {
                const char* p = aptr + mt * 16 * PITCHB + kb;
                a[mt][0] = *(const uint32_t*)(p);
                a[mt][1] = *(const uint32_t*)(p + 8 * PITCHB);
                a[mt][2] = *(const uint32_t*)(p + 16);
                a[mt][3] = *(const uint32_t*)(p + 8 * PITCHB + 16);
            }
            #pragma unroll
            for (int nt = 0; nt < 4; ++nt) {
                const char* p = bptr + nt * 8 * PITCHB + kb;
                b[nt][0] = *(const uint32_t*)(p);
                b[nt][1] = *(const uint32_t*)(p + 16);
            }
            #pragma unroll
            for (int mt = 0; mt < 4; ++mt)
                #pragma unroll
                for (int nt = 0; nt < 4; ++nt)
                    mma_bf16(acc[mt][nt], a[mt], b[nt]);
        }
    }

    // ---------------- epilogue: sim = 1/(nI+nJ-2dot+1), row + col sums ------
    float rs[4][2], cs[4][2];
    #pragma unroll
    for (int i = 0; i < 4; ++i) rs[i][0] = rs[i][1] = cs[i][0] = cs[i][1] = 0.0f;

    float nI[4][2], nJ[4][2];
    #pragma unroll
    for (int mt = 0; mt < 4; ++mt) {
        nI[mt][0] = nIs[wm * 64 + mt * 16 + g];
        nI[mt][1] = nIs[wm * 64 + mt * 16 + g + 8];
    }
    #pragma unroll
    for (int nt = 0; nt < 4; ++nt) {
        nJ[nt][0] = nJs[wn * 32 + nt * 8 + 2 * t];
        nJ[nt][1] = nJs[wn * 32 + nt * 8 + 2 * t + 1];
    }

    #pragma unroll
    for (int mt = 0; mt < 4; ++mt)
        #pragma unroll
        for (int nt = 0; nt < 4; ++nt)
            #pragma unroll
            for (int r = 0; r < 2; ++r)
                #pragma unroll
                for (int e = 0; e < 2; ++e) {
                    float dot = acc[mt][nt][r * 2 + e];
                    float sq = fmaf(-2.0f, dot, nI[mt][r] + nJ[nt][e]);
                    sq = fmaxf(sq, 0.0f);
                    float sim = __fdividef(1.0f, sq + 1.0f);
                    rs[mt][r] += sim;
                    cs[nt][e] += sim;
                }

    // row sums: reduce across quad (t), leader t==0 owns rows
    #pragma unroll
    for (int mt = 0; mt < 4; ++mt)
        #pragma unroll
        for (int r = 0; r < 2; ++r) {
            float v = rs[mt][r];
            v += __shfl_xor_sync(0xffffffffu, v, 1);
            v += __shfl_xor_sync(0xffffffffu, v, 2);
            if (t == 0)
                atomicAdd(&g_rowsum[row0 + wm * 64 + mt * 16 + g + r * 8], v);
        }

    // col sums (only off-diagonal tiles): reduce across g, leaders lane<4
    if (bi != bj) {
        #pragma unroll
        for (int nt = 0; nt < 4; ++nt)
            #pragma unroll
            for (int e = 0; e < 2; ++e) {
                float v = cs[nt][e];
                v += __shfl_xor_sync(0xffffffffu, v, 4);
                v += __shfl_xor_sync(0xffffffffu, v, 8);
                v += __shfl_xor_sync(0xffffffffu, v, 16);
                if (g == 0)
                    atomicAdd(&g_rowsum[col0 + wn * 32 + nt * 8 + 2 * t + e], v);
            }
    }
}

// ---------------------------------------------------------------------------
// Kernel 3: final scalar.
// ---------------------------------------------------------------------------
__global__ void finalize_kernel(float* __restrict__ out) {
    __shared__ float sA[1024], s1[1024], s2[1024];
    int tid = threadIdx.x;
    float tA = 0.0f, t1 = 0.0f, t2 = 0.0f;
    for (int i = tid; i < HALF_N; i += 1024) {
        tA += logf(g_diag[i]);
        t2 += logf(g_rowsum[i] - 1.0f);
        t1 += logf(g_rowsum[i + HALF_N] - 1.0f);
    }
    sA[tid] = tA; s1[tid] = t1; s2[tid] = t2;
    __syncthreads();
    for (int s = 512; s; s >>= 1) {
        if (tid < s) {
            sA[tid] += sA[tid + s];
            s1[tid] += s1[tid + s];
            s2[tid] += s2[tid + s];
        }
        __syncthreads();
    }
    if (tid == 0) {
        float align = sA[0] * (1.0f / HALF_N);
        float lse1  = s1[0] * (1.0f / HALF_N);
        float lse2  = s2[0] * (1.0f / HALF_N);
        out[0] = -(align - 0.5f * (lse1 + lse2));
    }
}

// ---------------------------------------------------------------------------
extern "C" void kernel_launch(void* const* d_in, const int* in_sizes, int n_in,
                              void* d_out, int out_size) {
    const float* X = (const float*)d_in[0];
    float* out = (float*)d_out;

    cudaFuncSetAttribute(simsum_kernel,
                         cudaFuncAttributeMaxDynamicSharedMemorySize, SMEM_TOTAL);

    prep_kernel<<<N_TOTAL / 8, 256>>>(X);
    dim3 grid(N_TOTAL / BM, N_TOTAL / BN);
    simsum_kernel<<<grid, 256, SMEM_TOTAL>>>();
    finalize_kernel<<<1, 1024>>>(out);
}

// round 4
// speedup vs baseline: 7.6391x; 1.7536x over previous
#include <cuda_runtime.h>
#include <cuda_fp16.h>
#include <math.h>
#include <stdint.h>

#define N_TOTAL 8192
#define HALF_N  4096
#define BM      128
#define BN      128
#define MTILES  64               // N_TOTAL / BM
#define PITCHB  272              // 256B fp16 row + 16B pad (conflict-free)

#define SMEM_A   0
#define SMEM_B   (128 * PITCHB)
#define SMEM_NI  (256 * PITCHB)               // 128 floats
#define SMEM_NJ  (256 * PITCHB + 512)         // 128 floats
#define SMEM_TOTAL (256 * PITCHB + 1024)      // 70656 B

__device__ __align__(16) __half g_Y[N_TOTAL * 128];   // 2 MB fp16 copy
__device__ float g_norm[N_TOTAL];
__device__ float g_rowsum[N_TOTAL];
__device__ float g_diag[HALF_N];

// ---------------------------------------------------------------- helpers
__device__ __forceinline__ uint32_t smem_u32(const void* p) {
    uint32_t a;
    asm("{ .reg .u64 t; cvta.to.shared.u64 t, %1; cvt.u32.u64 %0, t; }"
        : "=r"(a) : "l"(p));
    return a;
}
__device__ __forceinline__ void cp_async16(uint32_t dst, const void* src) {
    asm volatile("cp.async.cg.shared.global [%0], [%1], 16;"
                 :: "r"(dst), "l"(src) : "memory");
}
__device__ __forceinline__ void cp_commit() {
    asm volatile("cp.async.commit_group;" ::: "memory");
}
template <int N>
__device__ __forceinline__ void cp_wait() {
    asm volatile("cp.async.wait_group %0;" :: "n"(N) : "memory");
}
__device__ __forceinline__ void mma_f16(float* c, const uint32_t* a, const uint32_t* b) {
    asm volatile(
        "mma.sync.aligned.m16n8k16.row.col.f32.f16.f16.f32 "
        "{%0,%1,%2,%3}, {%4,%5,%6,%7}, {%8,%9}, {%0,%1,%2,%3};"
        : "+f"(c[0]), "+f"(c[1]), "+f"(c[2]), "+f"(c[3])
        : "r"(a[0]), "r"(a[1]), "r"(a[2]), "r"(a[3]), "r"(b[0]), "r"(b[1]));
}

// ---------------------------------------------------------------------------
// Kernel 1: norms (fp32), diag sims (fp32), rowsum zero, fp16 copy.
// One warp per row.
// ---------------------------------------------------------------------------
__global__ void prep_kernel(const float* __restrict__ X) {
    int warp = (blockIdx.x * blockDim.x + threadIdx.x) >> 5;
    int lane = threadIdx.x & 31;
    if (warp >= N_TOTAL) return;
    const float4* X4 = (const float4*)X;

    float4 v = X4[warp * 32 + lane];
    float s = v.x * v.x + v.y * v.y + v.z * v.z + v.w * v.w;
    #pragma unroll
    for (int off = 16; off; off >>= 1) s += __shfl_xor_sync(0xffffffffu, s, off);
    if (lane == 0) { g_norm[warp] = s; g_rowsum[warp] = 0.0f; }

    __half2* Yrow = (__half2*)(g_Y + (size_t)warp * 128);
    Yrow[lane * 2]     = __floats2half2_rn(v.x, v.y);
    Yrow[lane * 2 + 1] = __floats2half2_rn(v.z, v.w);

    if (warp < HALF_N) {
        float4 w = X4[(warp + HALF_N) * 32 + lane];
        float dx = v.x - w.x, dy = v.y - w.y, dz = v.z - w.z, dw = v.w - w.w;
        float sq = dx * dx + dy * dy + dz * dz + dw * dw;
        #pragma unroll
        for (int off = 16; off; off >>= 1) sq += __shfl_xor_sync(0xffffffffu, sq, off);
        if (lane == 0) g_diag[warp] = 1.0f / (fmaxf(sq, 0.0f) + 1.0f);
    }
}

// ---------------------------------------------------------------------------
// Kernel 2: upper-triangular 128x128 tiles, fp16 mma.sync, K=128.
// Linear grid of 2080 tiles. 256 threads = 2(m) x 4(n) warps, 64x32 warp tile.
// Off-diagonal tiles also contribute column sums (symmetry). Diagonal tiles
// force sim(i,i) = 1 exactly.
// ---------------------------------------------------------------------------
__global__ void __launch_bounds__(256, 2)
simsum_kernel() {
    // triangular decode: f(b) = b*(2*MTILES+1-b)/2 tiles before row b
    const int id = blockIdx.x;
    int bi = (int)((129.0f - sqrtf(fmaxf(16641.0f - 8.0f * (float)id, 0.0f))) * 0.5f);
    #pragma unroll 1
    while ((bi + 1) * (129 - (bi + 1)) / 2 <= id) ++bi;
    #pragma unroll 1
    while (bi * (129 - bi) / 2 > id) --bi;
    const int bj = bi + (id - bi * (129 - bi) / 2);
    const int row0 = bi * BM, col0 = bj * BN;
    const bool isdiag = (bi == bj);

    extern __shared__ char smem[];
    const uint32_t sb = smem_u32(smem);
    float* nIs = (float*)(smem + SMEM_NI);
    float* nJs = (float*)(smem + SMEM_NJ);

    const int tid = threadIdx.x;
    const int wid = tid >> 5, lid = tid & 31;
    const int wm = wid >> 2, wn = wid & 3;     // warp grid 2x4
    const int g = lid >> 2, t = lid & 3;

    if (tid < 128) nIs[tid] = g_norm[row0 + tid];
    else           nJs[tid - 128] = g_norm[col0 + tid - 128];

    // Two-stage cp.async: stage h covers k-bytes [h*128, h*128+128) of 256 rows.
    #pragma unroll
    for (int h = 0; h < 2; ++h) {
        #pragma unroll
        for (int it = 0; it < 8; ++it) {
            int chunk = it * 256 + tid;        // 0..2047
            int r = chunk >> 3;                // 0..255 (0-127: A, 128-255: B)
            int c = chunk & 7;                 // 16B chunk in 128B half-row
            int grow = (r < 128) ? (row0 + r) : (col0 + r - 128);
            const char* src = (const char*)g_Y + (size_t)grow * 256 + h * 128 + c * 16;
            cp_async16(sb + r * PITCHB + h * 128 + c * 16, src);
        }
        cp_commit();
    }

    float acc[4][4][4];
    #pragma unroll
    for (int mt = 0; mt < 4; ++mt)
        #pragma unroll
        for (int nt = 0; nt < 4; ++nt)
            #pragma unroll
            for (int e = 0; e < 4; ++e) acc[mt][nt][e] = 0.0f;

    const char* aptr = smem + SMEM_A + (wm * 64 + g) * PITCHB + t * 4;
    const char* bptr = smem + SMEM_B + (wn * 32 + g) * PITCHB + t * 4;

    #pragma unroll
    for (int h = 0; h < 2; ++h) {
        if (h == 0) cp_wait<1>(); else cp_wait<0>();
        __syncthreads();

        #pragma unroll
        for (int s = 0; s < 4; ++s) {
            const int kb = h * 128 + s * 32;   // 16 fp16 per k-step
            uint32_t a[4][4], b[4][2];
            #pragma unroll
            for (int mt = 0; mt < 4; ++mt) {
                const char* p = aptr + mt * 16 * PITCHB + kb;
                a[mt][0] = *(const uint32_t*)(p);
                a[mt][1] = *(const uint32_t*)(p + 8 * PITCHB);
                a[mt][2] = *(const uint32_t*)(p + 16);
                a[mt][3] = *(const uint32_t*)(p + 8 * PITCHB + 16);
            }
            #pragma unroll
            for (int nt = 0; nt < 4; ++nt) {
                const char* p = bptr + nt * 8 * PITCHB + kb;
                b[nt][0] = *(const uint32_t*)(p);
                b[nt][1] = *(const uint32_t*)(p + 16);
            }
            #pragma unroll
            for (int mt = 0; mt < 4; ++mt)
                #pragma unroll
                for (int nt = 0; nt < 4; ++nt)
                    mma_f16(acc[mt][nt], a[mt], b[nt]);
        }
    }

    // ---------------- epilogue ---------------------------------------------
    float rs[4][2], cs[4][2];
    #pragma unroll
    for (int i = 0; i < 4; ++i) rs[i][0] = rs[i][1] = cs[i][0] = cs[i][1] = 0.0f;

    #pragma unroll
    for (int mt = 0; mt < 4; ++mt)
        #pragma unroll
        for (int nt = 0; nt < 4; ++nt)
            #pragma unroll
            for (int r = 0; r < 2; ++r)
                #pragma unroll
                for (int e = 0; e < 2; ++e) {
                    int li = wm * 64 + mt * 16 + g + r * 8;   // local row
                    int lj = wn * 32 + nt * 8 + 2 * t + e;    // local col
                    float dot = acc[mt][nt][r * 2 + e];
                    float sq = fmaf(-2.0f, dot, nIs[li] + nJs[lj]);
                    sq = fmaxf(sq, 0.0f);
                    float sim = __fdividef(1.0f, sq + 1.0f);
                    if (isdiag && li == lj) sim = 1.0f;       // exact self-sim
                    rs[mt][r] += sim;
                    cs[nt][e] += sim;
                }

    // row sums: reduce across quad (t)
    #pragma unroll
    for (int mt = 0; mt < 4; ++mt)
        #pragma unroll
        for (int r = 0; r < 2; ++r) {
            float v = rs[mt][r];
            v += __shfl_xor_sync(0xffffffffu, v, 1);
            v += __shfl_xor_sync(0xffffffffu, v, 2);
            if (t == 0)
                atomicAdd(&g_rowsum[row0 + wm * 64 + mt * 16 + g + r * 8], v);
        }

    // col sums (off-diagonal tiles only): reduce across g
    if (!isdiag) {
        #pragma unroll
        for (int nt = 0; nt < 4; ++nt)
            #pragma unroll
            for (int e = 0; e < 2; ++e) {
                float v = cs[nt][e];
                v += __shfl_xor_sync(0xffffffffu, v, 4);
                v += __shfl_xor_sync(0xffffffffu, v, 8);
                v += __shfl_xor_sync(0xffffffffu, v, 16);
                if (g == 0)
                    atomicAdd(&g_rowsum[col0 + wn * 32 + nt * 8 + 2 * t + e], v);
            }
    }
}

// ---------------------------------------------------------------------------
// Kernel 3: final scalar.
// ---------------------------------------------------------------------------
__global__ void finalize_kernel(float* __restrict__ out) {
    __shared__ float sA[1024], s1[1024], s2[1024];
    int tid = threadIdx.x;
    float tA = 0.0f, t1 = 0.0f, t2 = 0.0f;
    for (int i = tid; i < HALF_N; i += 1024) {
        tA += logf(g_diag[i]);
        t2 += logf(g_rowsum[i] - 1.0f);
        t1 += logf(g_rowsum[i + HALF_N] - 1.0f);
    }
    sA[tid] = tA; s1[tid] = t1; s2[tid] = t2;
    __syncthreads();
    for (int s = 512; s; s >>= 1) {
        if (tid < s) {
            sA[tid] += sA[tid + s];
            s1[tid] += s1[tid + s];
            s2[tid] += s2[tid + s];
        }
        __syncthreads();
    }
    if (tid == 0) {
        float align = sA[0] * (1.0f / HALF_N);
        float lse1  = s1[0] * (1.0f / HALF_N);
        float lse2  = s2[0] * (1.0f / HALF_N);
        out[0] = -(align - 0.5f * (lse1 + lse2));
    }
}

// ---------------------------------------------------------------------------
extern "C" void kernel_launch(void* const* d_in, const int* in_sizes, int n_in,
                              void* d_out, int out_size) {
    const float* X = (const float*)d_in[0];
    float* out = (float*)d_out;

    cudaFuncSetAttribute(simsum_kernel,
                         cudaFuncAttributeMaxDynamicSharedMemorySize, SMEM_TOTAL);

    prep_kernel<<<N_TOTAL / 8, 256>>>(X);
    simsum_kernel<<<MTILES * (MTILES + 1) / 2, 256, SMEM_TOTAL>>>();
    finalize_kernel<<<1, 1024>>>(out);
}

// round 5
// speedup vs baseline: 8.2579x; 1.0810x over previous
#include <cuda_runtime.h>
#include <cuda_fp16.h>
#include <math.h>
#include <stdint.h>

#define N_TOTAL 8192
#define HALF_N  4096
#define BM      128
#define BN      128
#define MTILES  64               // N_TOTAL / BM
#define NTILES  2080             // MTILES*(MTILES+1)/2
#define NCTAS   304              // 2 per SM (152 SMs)
#define PITCHB  272              // 256B fp16 row + 16B pad

#define SMEM_A    0
#define SMEM_B0   34816
#define SMEM_B1   69632
#define SMEM_NI   104448
#define SMEM_NJ0  104960
#define SMEM_NJ1  105472
#define SMEM_TOTAL 105984

__device__ __align__(16) __half g_Y[N_TOTAL * 128];   // 2 MB fp16 copy
__device__ float g_norm[N_TOTAL];
__device__ float g_rowsum[N_TOTAL];
__device__ float g_diag[HALF_N];

// ---------------------------------------------------------------- helpers
__device__ __forceinline__ uint32_t smem_u32(const void* p) {
    uint32_t a;
    asm("{ .reg .u64 t; cvta.to.shared.u64 t, %1; cvt.u32.u64 %0, t; }"
        : "=r"(a) : "l"(p));
    return a;
}
__device__ __forceinline__ void cp_async16(uint32_t dst, const void* src) {
    asm volatile("cp.async.cg.shared.global [%0], [%1], 16;"
                 :: "r"(dst), "l"(src) : "memory");
}
__device__ __forceinline__ void cp_commit() {
    asm volatile("cp.async.commit_group;" ::: "memory");
}
template <int N>
__device__ __forceinline__ void cp_wait() {
    asm volatile("cp.async.wait_group %0;" :: "n"(N) : "memory");
}
__device__ __forceinline__ void mma_f16(float* c, const uint32_t* a, const uint32_t* b) {
    asm volatile(
        "mma.sync.aligned.m16n8k16.row.col.f32.f16.f16.f32 "
        "{%0,%1,%2,%3}, {%4,%5,%6,%7}, {%8,%9}, {%0,%1,%2,%3};"
        : "+f"(c[0]), "+f"(c[1]), "+f"(c[2]), "+f"(c[3])
        : "r"(a[0]), "r"(a[1]), "r"(a[2]), "r"(a[3]), "r"(b[0]), "r"(b[1]));
}

// ---------------------------------------------------------------------------
// Kernel 1: norms (fp32), diag sims (fp32), rowsum zero, fp16 copy.
// ---------------------------------------------------------------------------
__global__ void prep_kernel(const float* __restrict__ X) {
    int warp = (blockIdx.x * blockDim.x + threadIdx.x) >> 5;
    int lane = threadIdx.x & 31;
    if (warp >= N_TOTAL) return;
    const float4* X4 = (const float4*)X;

    float4 v = X4[warp * 32 + lane];
    float s = v.x * v.x + v.y * v.y + v.z * v.z + v.w * v.w;
    #pragma unroll
    for (int off = 16; off; off >>= 1) s += __shfl_xor_sync(0xffffffffu, s, off);
    if (lane == 0) { g_norm[warp] = s; g_rowsum[warp] = 0.0f; }

    __half2* Yrow = (__half2*)(g_Y + (size_t)warp * 128);
    Yrow[lane * 2]     = __floats2half2_rn(v.x, v.y);
    Yrow[lane * 2 + 1] = __floats2half2_rn(v.z, v.w);

    if (warp < HALF_N) {
        float4 w = X4[(warp + HALF_N) * 32 + lane];
        float dx = v.x - w.x, dy = v.y - w.y, dz = v.z - w.z, dw = v.w - w.w;
        float sq = dx * dx + dy * dy + dz * dz + dw * dw;
        #pragma unroll
        for (int off = 16; off; off >>= 1) sq += __shfl_xor_sync(0xffffffffu, sq, off);
        if (lane == 0) g_diag[warp] = 1.0f / (fmaxf(sq, 0.0f) + 1.0f);
    }
}

// ---------------------------------------------------------------------------
// Kernel 2: persistent upper-triangular tile GEMM. 304 CTAs, each runs a
// contiguous chunk of triangular tile ids. A tile reused across a row run;
// B (+nJ) double-buffered and prefetched during the previous tile's MMAs.
// ---------------------------------------------------------------------------
__global__ void __launch_bounds__(256, 2)
simsum_kernel() {
    extern __shared__ char smem[];
    const uint32_t sb = smem_u32(smem);
    float* nIs = (float*)(smem + SMEM_NI);

    const int tid = threadIdx.x;
    const int wid = tid >> 5, lid = tid & 31;
    const int wm = wid >> 2, wn = wid & 3;     // warp grid 2x4
    const int g = lid >> 2, t = lid & 3;

    // static chunking: first 256 CTAs get 7 tiles, rest get 6 (256*7+48*6=2080)
    const int c = blockIdx.x;
    const int start = 6 * c + min(c, 256);
    const int cnt = 6 + (c < 256 ? 1 : 0);

    // decode row-tile: tiles before row b = b*(129-b)/2
    int cbi = 0;
    #pragma unroll 1
    while ((cbi + 1) * (129 - (cbi + 1)) / 2 <= start) ++cbi;
    int cbj = cbi + (start - cbi * (129 - cbi) / 2);

    // ---- initial loads: A(cbi), nIs, B0(cbj), nJ0 ----
    {
        const char* Yb = (const char*)g_Y;
        #pragma unroll
        for (int it = 0; it < 8; ++it) {
            int chunk = it * 256 + tid;            // 2048 chunks
            int r = chunk >> 4, cc = chunk & 15;
            cp_async16(sb + SMEM_A + r * PITCHB + cc * 16,
                       Yb + (size_t)(cbi * BM + r) * 256 + cc * 16);
            cp_async16(sb + SMEM_B0 + r * PITCHB + cc * 16,
                       Yb + (size_t)(cbj * BN + r) * 256 + cc * 16);
        }
        if (tid < 32) {
            cp_async16(sb + SMEM_NI + tid * 16, g_norm + cbi * BM + tid * 4);
            cp_async16(sb + SMEM_NJ0 + tid * 16, g_norm + cbj * BN + tid * 4);
        }
        cp_commit();
    }

    #pragma unroll 1
    for (int it = 0; it < cnt; ++it) {
        const int buf = it & 1;
        const uint32_t bbase = buf ? SMEM_B1 : SMEM_B0;
        const uint32_t njoff = buf ? SMEM_NJ1 : SMEM_NJ0;
        const int row0 = cbi * BM, col0 = cbj * BN;
        const bool isdiag = (cbi == cbj);

        cp_wait<0>();
        __syncthreads();

        // next tile indices; prefetch its B (+nJ) into the other buffer
        int nbi = cbi, nbj = cbj;
        bool rowchg = false;
        if (it + 1 < cnt) {
            if (cbj == MTILES - 1) { nbi = cbi + 1; nbj = nbi; rowchg = true; }
            else nbj = cbj + 1;
            const uint32_t nb = buf ? SMEM_B0 : SMEM_B1;
            const char* Yb = (const char*)g_Y;
            #pragma unroll
            for (int i2 = 0; i2 < 8; ++i2) {
                int chunk = i2 * 256 + tid;
                int r = chunk >> 4, cc = chunk & 15;
                cp_async16(sb + nb + r * PITCHB + cc * 16,
                           Yb + (size_t)(nbj * BN + r) * 256 + cc * 16);
            }
            if (tid < 32)
                cp_async16(sb + (buf ? SMEM_NJ0 : SMEM_NJ1) + tid * 16,
                           g_norm + nbj * BN + tid * 4);
            cp_commit();
        }

        // ---- MMA: 128x128, K=128 ----
        float acc[4][4][4];
        #pragma unroll
        for (int mt = 0; mt < 4; ++mt)
            #pragma unroll
            for (int nt = 0; nt < 4; ++nt)
                #pragma unroll
                for (int e = 0; e < 4; ++e) acc[mt][nt][e] = 0.0f;

        const char* aptr = smem + SMEM_A + (wm * 64 + g) * PITCHB + t * 4;
        const char* bptr = smem + bbase + (wn * 32 + g) * PITCHB + t * 4;

        #pragma unroll
        for (int s = 0; s < 8; ++s) {
            const int kb = s * 32;
            uint32_t a[4][4], b[4][2];
            #pragma unroll
            for (int mt = 0; mt < 4; ++mt) {
                const char* p = aptr + mt * 16 * PITCHB + kb;
                a[mt][0] = *(const uint32_t*)(p);
                a[mt][1] = *(const uint32_t*)(p + 8 * PITCHB);
                a[mt][2] = *(const uint32_t*)(p + 16);
                a[mt][3] = *(const uint32_t*)(p + 8 * PITCHB + 16);
            }
            #pragma unroll
            for (int nt = 0; nt < 4; ++nt) {
                const char* p = bptr + nt * 8 * PITCHB + kb;
                b[nt][0] = *(const uint32_t*)(p);
                b[nt][1] = *(const uint32_t*)(p + 16);
            }
            #pragma unroll
            for (int mt = 0; mt < 4; ++mt)
                #pragma unroll
                for (int nt = 0; nt < 4; ++nt)
                    mma_f16(acc[mt][nt], a[mt], b[nt]);
        }

        // ---- epilogue ----
        const float* nJs = (const float*)(smem + njoff);
        float rs[4][2], cs[4][2];
        #pragma unroll
        for (int i = 0; i < 4; ++i) rs[i][0] = rs[i][1] = cs[i][0] = cs[i][1] = 0.0f;

        #pragma unroll
        for (int mt = 0; mt < 4; ++mt)
            #pragma unroll
            for (int nt = 0; nt < 4; ++nt)
                #pragma unroll
                for (int r = 0; r < 2; ++r)
                    #pragma unroll
                    for (int e = 0; e < 2; ++e) {
                        int li = wm * 64 + mt * 16 + g + r * 8;
                        int lj = wn * 32 + nt * 8 + 2 * t + e;
                        float dot = acc[mt][nt][r * 2 + e];
                        float sq = fmaf(-2.0f, dot, nIs[li] + nJs[lj]);
                        sq = fmaxf(sq, 0.0f);
                        float sim = __fdividef(1.0f, sq + 1.0f);
                        if (isdiag && li == lj) sim = 1.0f;
                        rs[mt][r] += sim;
                        cs[nt][e] += sim;
                    }

        #pragma unroll
        for (int mt = 0; mt < 4; ++mt)
            #pragma unroll
            for (int r = 0; r < 2; ++r) {
                float v = rs[mt][r];
                v += __shfl_xor_sync(0xffffffffu, v, 1);
                v += __shfl_xor_sync(0xffffffffu, v, 2);
                if (t == 0)
                    atomicAdd(&g_rowsum[row0 + wm * 64 + mt * 16 + g + r * 8], v);
            }
        if (!isdiag) {
            #pragma unroll
            for (int nt = 0; nt < 4; ++nt)
                #pragma unroll
                for (int e = 0; e < 2; ++e) {
                    float v = cs[nt][e];
                    v += __shfl_xor_sync(0xffffffffu, v, 4);
                    v += __shfl_xor_sync(0xffffffffu, v, 8);
                    v += __shfl_xor_sync(0xffffffffu, v, 16);
                    if (g == 0)
                        atomicAdd(&g_rowsum[col0 + wn * 32 + nt * 8 + 2 * t + e], v);
                }
        }

        // row change: reload A + nIs (must wait until all warps left old A)
        if (rowchg) {
            __syncthreads();
            const char* Yb = (const char*)g_Y;
            #pragma unroll
            for (int i2 = 0; i2 < 8; ++i2) {
                int chunk = i2 * 256 + tid;
                int r = chunk >> 4, cc = chunk & 15;
                cp_async16(sb + SMEM_A + r * PITCHB + cc * 16,
                           Yb + (size_t)(nbi * BM + r) * 256 + cc * 16);
            }
            if (tid < 32)
                cp_async16(sb + SMEM_NI + tid * 16, g_norm + nbi * BM + tid * 4);
            cp_commit();
        }
        cbi = nbi; cbj = nbj;
    }
}

// ---------------------------------------------------------------------------
// Kernel 3: final scalar.
// ---------------------------------------------------------------------------
__global__ void finalize_kernel(float* __restrict__ out) {
    __shared__ float sA[1024], s1[1024], s2[1024];
    int tid = threadIdx.x;
    float tA = 0.0f, t1 = 0.0f, t2 = 0.0f;
    for (int i = tid; i < HALF_N; i += 1024) {
        tA += __logf(g_diag[i]);
        t2 += __logf(g_rowsum[i] - 1.0f);
        t1 += __logf(g_rowsum[i + HALF_N] - 1.0f);
    }
    sA[tid] = tA; s1[tid] = t1; s2[tid] = t2;
    __syncthreads();
    for (int s = 512; s; s >>= 1) {
        if (tid < s) {
            sA[tid] += sA[tid + s];
            s1[tid] += s1[tid + s];
            s2[tid] += s2[tid + s];
        }
        __syncthreads();
    }
    if (tid == 0) {
        float align = sA[0] * (1.0f / HALF_N);
        float lse1  = s1[0] * (1.0f / HALF_N);
        float lse2  = s2[0] * (1.0f / HALF_N);
        out[0] = -(align - 0.5f * (lse1 + lse2));
    }
}

// ---------------------------------------------------------------------------
extern "C" void kernel_launch(void* const* d_in, const int* in_sizes, int n_in,
                              void* d_out, int out_size) {
    const float* X = (const float*)d_in[0];
    float* out = (float*)d_out;

    cudaFuncSetAttribute(simsum_kernel,
                         cudaFuncAttributeMaxDynamicSharedMemorySize, SMEM_TOTAL);

    prep_kernel<<<N_TOTAL / 8, 256>>>(X);
    simsum_kernel<<<NCTAS, 256, SMEM_TOTAL>>>();
    finalize_kernel<<<1, 1024>>>(out);
}

// round 6
// speedup vs baseline: 8.5117x; 1.0307x over previous
#include <cuda_runtime.h>
#include <cuda_fp16.h>
#include <math.h>
#include <stdint.h>

#define N_TOTAL 8192
#define HALF_N  4096
#define BM      128
#define BN      128
#define MTILES  64               // N_TOTAL / BM
#define NTILES  2080             // MTILES*(MTILES+1)/2
#define NCTAS   304              // 2 per SM (152 SMs)
#define PITCHB  272              // 256B fp16 row + 16B pad

#define SMEM_A    0
#define SMEM_B0   34816
#define SMEM_B1   69632
#define SMEM_NI   104448
#define SMEM_NJ0  104960
#define SMEM_NJ1  105472
#define SMEM_TOTAL 105984

__device__ __align__(16) __half g_Y[N_TOTAL * 128];   // 2 MB fp16 copy
__device__ float g_norm[N_TOTAL];
__device__ float g_rowsum[N_TOTAL];
__device__ float g_diag[HALF_N];

// ---------------------------------------------------------------- helpers
__device__ __forceinline__ uint32_t smem_u32(const void* p) {
    uint32_t a;
    asm("{ .reg .u64 t; cvta.to.shared.u64 t, %1; cvt.u32.u64 %0, t; }"
        : "=r"(a) : "l"(p));
    return a;
}
__device__ __forceinline__ void cp_async16(uint32_t dst, const void* src) {
    asm volatile("cp.async.cg.shared.global [%0], [%1], 16;"
                 :: "r"(dst), "l"(src) : "memory");
}
__device__ __forceinline__ void cp_commit() {
    asm volatile("cp.async.commit_group;" ::: "memory");
}
template <int N>
__device__ __forceinline__ void cp_wait() {
    asm volatile("cp.async.wait_group %0;" :: "n"(N) : "memory");
}
__device__ __forceinline__ void mma_f16(float* c, const uint32_t* a, const uint32_t* b) {
    asm volatile(
        "mma.sync.aligned.m16n8k16.row.col.f32.f16.f16.f32 "
        "{%0,%1,%2,%3}, {%4,%5,%6,%7}, {%8,%9}, {%0,%1,%2,%3};"
        : "+f"(c[0]), "+f"(c[1]), "+f"(c[2]), "+f"(c[3])
        : "r"(a[0]), "r"(a[1]), "r"(a[2]), "r"(a[3]), "r"(b[0]), "r"(b[1]));
}
__device__ __forceinline__ void ldsm_x4(uint32_t* r, uint32_t addr) {
    asm volatile("ldmatrix.sync.aligned.m8n8.x4.shared.b16 {%0,%1,%2,%3}, [%4];"
                 : "=r"(r[0]), "=r"(r[1]), "=r"(r[2]), "=r"(r[3])
                 : "r"(addr));
}

// ---------------------------------------------------------------------------
// Kernel 1: norms (fp32), diag sims (fp32), rowsum zero, fp16 copy.
// ---------------------------------------------------------------------------
__global__ void prep_kernel(const float* __restrict__ X) {
    int warp = (blockIdx.x * blockDim.x + threadIdx.x) >> 5;
    int lane = threadIdx.x & 31;
    if (warp >= N_TOTAL) return;
    const float4* X4 = (const float4*)X;

    float4 v = X4[warp * 32 + lane];
    float s = v.x * v.x + v.y * v.y + v.z * v.z + v.w * v.w;
    #pragma unroll
    for (int off = 16; off; off >>= 1) s += __shfl_xor_sync(0xffffffffu, s, off);
    if (lane == 0) { g_norm[warp] = s; g_rowsum[warp] = 0.0f; }

    __half2* Yrow = (__half2*)(g_Y + (size_t)warp * 128);
    Yrow[lane * 2]     = __floats2half2_rn(v.x, v.y);
    Yrow[lane * 2 + 1] = __floats2half2_rn(v.z, v.w);

    if (warp < HALF_N) {
        float4 w = X4[(warp + HALF_N) * 32 + lane];
        float dx = v.x - w.x, dy = v.y - w.y, dz = v.z - w.z, dw = v.w - w.w;
        float sq = dx * dx + dy * dy + dz * dz + dw * dw;
        #pragma unroll
        for (int off = 16; off; off >>= 1) sq += __shfl_xor_sync(0xffffffffu, sq, off);
        if (lane == 0) g_diag[warp] = 1.0f / (fmaxf(sq, 0.0f) + 1.0f);
    }
}

// ---------------------------------------------------------------------------
// Kernel 2: persistent upper-triangular tile GEMM (ldmatrix fragment loads).
// ---------------------------------------------------------------------------
__global__ void __launch_bounds__(256, 2)
simsum_kernel() {
    extern __shared__ char smem[];
    const uint32_t sb = smem_u32(smem);
    float* nIs = (float*)(smem + SMEM_NI);

    const int tid = threadIdx.x;
    const int wid = tid >> 5, lid = tid & 31;
    const int wm = wid >> 2, wn = wid & 3;     // warp grid 2x4
    const int g = lid >> 2, t = lid & 3;

    // static chunking: first 256 CTAs get 7 tiles, rest get 6 (256*7+48*6=2080)
    const int c = blockIdx.x;
    const int start = 6 * c + min(c, 256);
    const int cnt = 6 + (c < 256 ? 1 : 0);

    int cbi = 0;
    #pragma unroll 1
    while ((cbi + 1) * (129 - (cbi + 1)) / 2 <= start) ++cbi;
    int cbj = cbi + (start - cbi * (129 - cbi) / 2);

    // ldmatrix lane-relative offsets
    // A (x4 per mt): lanes 0-15 -> rows 0-15 koff 0; lanes 16-31 -> rows 0-15 koff 16B
    const uint32_t arel = (uint32_t)((wm * 64 + (lid & 15)) * PITCHB + (lid >> 4) * 16);
    // B (x4 per nt-pair): lanes 0-15 -> nt even (rows+0), lanes 16-31 -> nt odd (rows+8);
    // within half: lane bit3 selects koff 16B
    const uint32_t brel = (uint32_t)((wn * 32 + (lid >> 4) * 8 + (lid & 7)) * PITCHB
                                     + ((lid >> 3) & 1) * 16);

    // ---- initial loads: A(cbi), nIs, B0(cbj), nJ0 ----
    {
        const char* Yb = (const char*)g_Y;
        #pragma unroll
        for (int it = 0; it < 8; ++it) {
            int chunk = it * 256 + tid;
            int r = chunk >> 4, cc = chunk & 15;
            cp_async16(sb + SMEM_A + r * PITCHB + cc * 16,
                       Yb + (size_t)(cbi * BM + r) * 256 + cc * 16);
            cp_async16(sb + SMEM_B0 + r * PITCHB + cc * 16,
                       Yb + (size_t)(cbj * BN + r) * 256 + cc * 16);
        }
        if (tid < 32) {
            cp_async16(sb + SMEM_NI + tid * 16, g_norm + cbi * BM + tid * 4);
            cp_async16(sb + SMEM_NJ0 + tid * 16, g_norm + cbj * BN + tid * 4);
        }
        cp_commit();
    }

    #pragma unroll 1
    for (int it = 0; it < cnt; ++it) {
        const int buf = it & 1;
        const uint32_t bbase = buf ? SMEM_B1 : SMEM_B0;
        const uint32_t njoff = buf ? SMEM_NJ1 : SMEM_NJ0;
        const int row0 = cbi * BM, col0 = cbj * BN;
        const bool isdiag = (cbi == cbj);

        cp_wait<0>();
        __syncthreads();

        // next tile indices; prefetch its B (+nJ) into the other buffer
        int nbi = cbi, nbj = cbj;
        bool rowchg = false;
        if (it + 1 < cnt) {
            if (cbj == MTILES - 1) { nbi = cbi + 1; nbj = nbi; rowchg = true; }
            else nbj = cbj + 1;
            const uint32_t nb = buf ? SMEM_B0 : SMEM_B1;
            const char* Yb = (const char*)g_Y;
            #pragma unroll
            for (int i2 = 0; i2 < 8; ++i2) {
                int chunk = i2 * 256 + tid;
                int r = chunk >> 4, cc = chunk & 15;
                cp_async16(sb + nb + r * PITCHB + cc * 16,
                           Yb + (size_t)(nbj * BN + r) * 256 + cc * 16);
            }
            if (tid < 32)
                cp_async16(sb + (buf ? SMEM_NJ0 : SMEM_NJ1) + tid * 16,
                           g_norm + nbj * BN + tid * 4);
            cp_commit();
        }

        // ---- MMA: 128x128, K=128, ldmatrix fragment loads ----
        float acc[4][4][4];
        #pragma unroll
        for (int mt = 0; mt < 4; ++mt)
            #pragma unroll
            for (int nt = 0; nt < 4; ++nt)
                #pragma unroll
                for (int e = 0; e < 4; ++e) acc[mt][nt][e] = 0.0f;

        const uint32_t aA = sb + SMEM_A + arel;
        const uint32_t aB = sb + bbase + brel;

        #pragma unroll
        for (int s = 0; s < 8; ++s) {
            const uint32_t kb = (uint32_t)(s * 32);
            uint32_t a[4][4], b[2][4];
            #pragma unroll
            for (int mt = 0; mt < 4; ++mt)
                ldsm_x4(a[mt], aA + mt * 16 * PITCHB + kb);
            #pragma unroll
            for (int p = 0; p < 2; ++p)
                ldsm_x4(b[p], aB + p * 16 * PITCHB + kb);
            // b[p] = {b[2p][0], b[2p][1], b[2p+1][0], b[2p+1][1]}
            #pragma unroll
            for (int mt = 0; mt < 4; ++mt) {
                mma_f16(acc[mt][0], a[mt], &b[0][0]);
                mma_f16(acc[mt][1], a[mt], &b[0][2]);
                mma_f16(acc[mt][2], a[mt], &b[1][0]);
                mma_f16(acc[mt][3], a[mt], &b[1][2]);
            }
        }

        // ---- epilogue ----
        const float* nJs = (const float*)(smem + njoff);
        float rs[4][2], cs[4][2];
        #pragma unroll
        for (int i = 0; i < 4; ++i) rs[i][0] = rs[i][1] = cs[i][0] = cs[i][1] = 0.0f;

        #pragma unroll
        for (int mt = 0; mt < 4; ++mt)
            #pragma unroll
            for (int nt = 0; nt < 4; ++nt)
                #pragma unroll
                for (int r = 0; r < 2; ++r)
                    #pragma unroll
                    for (int e = 0; e < 2; ++e) {
                        int li = wm * 64 + mt * 16 + g + r * 8;
                        int lj = wn * 32 + nt * 8 + 2 * t + e;
                        float dot = acc[mt][nt][r * 2 + e];
                        float sq = fmaf(-2.0f, dot, nIs[li] + nJs[lj]);
                        sq = fmaxf(sq, 0.0f);
                        float sim = __fdividef(1.0f, sq + 1.0f);
                        if (isdiag && li == lj) sim = 1.0f;
                        rs[mt][r] += sim;
                        cs[nt][e] += sim;
                    }

        #pragma unroll
        for (int mt = 0; mt < 4; ++mt)
            #pragma unroll
            for (int r = 0; r < 2; ++r) {
                float v = rs[mt][r];
                v += __shfl_xor_sync(0xffffffffu, v, 1);
                v += __shfl_xor_sync(0xffffffffu, v, 2);
                if (t == 0)
                    atomicAdd(&g_rowsum[row0 + wm * 64 + mt * 16 + g + r * 8], v);
            }
        if (!isdiag) {
            #pragma unroll
            for (int nt = 0; nt < 4; ++nt)
                #pragma unroll
                for (int e = 0; e < 2; ++e) {
                    float v = cs[nt][e];
                    v += __shfl_xor_sync(0xffffffffu, v, 4);
                    v += __shfl_xor_sync(0xffffffffu, v, 8);
                    v += __shfl_xor_sync(0xffffffffu, v, 16);
                    if (g == 0)
                        atomicAdd(&g_rowsum[col0 + wn * 32 + nt * 8 + 2 * t + e], v);
                }
        }

        // row change: reload A + nIs (after all warps are done with old A)
        if (rowchg) {
            __syncthreads();
            const char* Yb = (const char*)g_Y;
            #pragma unroll
            for (int i2 = 0; i2 < 8; ++i2) {
                int chunk = i2 * 256 + tid;
                int r = chunk >> 4, cc = chunk & 15;
                cp_async16(sb + SMEM_A + r * PITCHB + cc * 16,
                           Yb + (size_t)(nbi * BM + r) * 256 + cc * 16);
            }
            if (tid < 32)
                cp_async16(sb + SMEM_NI + tid * 16, g_norm + nbi * BM + tid * 4);
            cp_commit();
        }
        cbi = nbi; cbj = nbj;
    }
}

// ---------------------------------------------------------------------------
// Kernel 3: final scalar.
// ---------------------------------------------------------------------------
__global__ void finalize_kernel(float* __restrict__ out) {
    __shared__ float sA[1024], s1[1024], s2[1024];
    int tid = threadIdx.x;
    float tA = 0.0f, t1 = 0.0f, t2 = 0.0f;
    for (int i = tid; i < HALF_N; i += 1024) {
        tA += __logf(g_diag[i]);
        t2 += __logf(g_rowsum[i] - 1.0f);
        t1 += __logf(g_rowsum[i + HALF_N] - 1.0f);
    }
    sA[tid] = tA; s1[tid] = t1; s2[tid] = t2;
    __syncthreads();
    for (int s = 512; s; s >>= 1) {
        if (tid < s) {
            sA[tid] += sA[tid + s];
            s1[tid] += s1[tid + s];
            s2[tid] += s2[tid + s];
        }
        __syncthreads();
    }
    if (tid == 0) {
        float align = sA[0] * (1.0f / HALF_N);
        float lse1  = s1[0] * (1.0f / HALF_N);
        float lse2  = s2[0] * (1.0f / HALF_N);
        out[0] = -(align - 0.5f * (lse1 + lse2));
    }
}

// ---------------------------------------------------------------------------
extern "C" void kernel_launch(void* const* d_in, const int* in_sizes, int n_in,
                              void* d_out, int out_size) {
    const float* X = (const float*)d_in[0];
    float* out = (float*)d_out;

    cudaFuncSetAttribute(simsum_kernel,
                         cudaFuncAttributeMaxDynamicSharedMemorySize, SMEM_TOTAL);

    prep_kernel<<<N_TOTAL / 8, 256>>>(X);
    simsum_kernel<<<NCTAS, 256, SMEM_TOTAL>>>();
    finalize_kernel<<<1, 1024>>>(out);
}